// round 1
// baseline (speedup 1.0000x reference)
#include <cuda_runtime.h>
#include <cstddef>

#define Nn 100000
#define Ee 1600000
#define Gg 100

// ---------------- scratch (device globals; no allocation allowed) ----------
__device__ float g_P[(size_t)Nn * 132];
__device__ float g_Q[(size_t)Nn * 132];
__device__ float g_m[(size_t)Nn * 32];
__device__ float g_f0[(size_t)Nn * 32];
__device__ float g_f1[(size_t)Nn * 32];
__device__ float g_rd[Ee];
__device__ float g_gsum[Gg];
__device__ float g_gcnt[Gg];

__device__ __forceinline__ float silu(float v) {
    // v * sigmoid(v) = v / (1 + e^-v); MUFU path (EX2 + RCP)
    float e = __expf(-v);
    return __fdividef(v, 1.0f + e);
}

// ---------------- rel_dist (shared by all 3 layers) -------------------------
__global__ void rd_kernel(const int* __restrict__ ei, const float* __restrict__ pos,
                          float* __restrict__ rd) {
    int e = blockIdx.x * blockDim.x + threadIdx.x;
    if (e >= Ee) return;
    int j = ei[e];
    int i = ei[Ee + e];
    float2 pj = reinterpret_cast<const float2*>(pos)[j];
    float2 pi = reinterpret_cast<const float2*>(pos)[i];
    float dx = pj.x - pi.x, dy = pj.y - pi.y;
    rd[e] = dx * dx + dy * dy;
}

// ---------------- zero helpers ----------------------------------------------
__global__ void zero_kernel(float* __restrict__ p, int n) {
    int idx = blockIdx.x * blockDim.x + threadIdx.x;
    if (idx < n) p[idx] = 0.0f;
}
__global__ void zero_pool_kernel(float* __restrict__ gs, float* __restrict__ gc) {
    int t = threadIdx.x;
    if (t < Gg) { gs[t] = 0.0f; gc[t] = 0.0f; }
}

// ---------------- per-node projection: P = feats@W1[0:FI]+b1, Q = feats@W1[FI:2FI]
// blockDim = round32(H), grid = (1, Nn/4); 4 nodes per block amortize weight loads
template <int FI, int H>
__global__ void pre_kernel(const float* __restrict__ featsrc, int lds,
                           const float* __restrict__ W1, const float* __restrict__ b1,
                           float* __restrict__ P, float* __restrict__ Q) {
    __shared__ float sf[4][FI];
    int n0 = blockIdx.y * 4;
    int t = threadIdx.x;
    if (t < 4 * FI) sf[t / FI][t % FI] = featsrc[(size_t)(n0 + t / FI) * lds + (t % FI)];
    __syncthreads();
    int h = t;
    if (h >= H) return;
    float p[4], q[4];
    float bb = b1[h];
#pragma unroll
    for (int u = 0; u < 4; u++) { p[u] = bb; q[u] = 0.0f; }
    for (int f = 0; f < FI; f++) {
        float wp = W1[f * H + h];
        float wq = W1[(FI + f) * H + h];
#pragma unroll
        for (int u = 0; u < 4; u++) {
            float xv = sf[u][f];
            p[u] += xv * wp;
            q[u] += xv * wq;
        }
    }
#pragma unroll
    for (int u = 0; u < 4; u++) {
        P[(size_t)(n0 + u) * H + h] = p[u];
        Q[(size_t)(n0 + u) * H + h] = q[u];
    }
}

// ---------------- edge kernel: m_ij = silu(silu(P_i + Q_j + a*wa + r*wd) @ W2 + b2)
// lane = edge; W2 uniform from shared (broadcast LDS.128); m[32] in registers
template <int H>
__global__ void edge_kernel(const int* __restrict__ ei, const float* __restrict__ ea,
                            const float* __restrict__ rd,
                            const float* __restrict__ P, const float* __restrict__ Q,
                            const float* __restrict__ wa, const float* __restrict__ wd,
                            const float* __restrict__ W2, const float* __restrict__ b2,
                            float* __restrict__ mi) {
    __shared__ __align__(16) float sWa[H];
    __shared__ __align__(16) float sWd[H];
    __shared__ __align__(16) float sW2[H * 32];
    __shared__ float sb2[32];
    for (int idx = threadIdx.x; idx < H; idx += blockDim.x) {
        sWa[idx] = wa[idx];
        sWd[idx] = wd[idx];
    }
    for (int idx = threadIdx.x; idx < H * 32; idx += blockDim.x) sW2[idx] = W2[idx];
    if (threadIdx.x < 32) sb2[threadIdx.x] = b2[threadIdx.x];
    __syncthreads();

    int e = blockIdx.x * blockDim.x + threadIdx.x;
    if (e >= Ee) return;
    int j = ei[e];
    int i = ei[Ee + e];
    float a = ea[e];
    float r = rd[e];

    float m[32];
#pragma unroll
    for (int c = 0; c < 32; c++) m[c] = sb2[c];

    const float4* Pr = reinterpret_cast<const float4*>(P + (size_t)i * H);
    const float4* Qr = reinterpret_cast<const float4*>(Q + (size_t)j * H);
    const float4* Wa4 = reinterpret_cast<const float4*>(sWa);
    const float4* Wd4 = reinterpret_cast<const float4*>(sWd);

    float4 p4 = Pr[0];
    float4 q4 = Qr[0];
#pragma unroll 1
    for (int kc = 0; kc < H / 4; kc++) {
        float4 pn, qn;
        if (kc + 1 < H / 4) { pn = Pr[kc + 1]; qn = Qr[kc + 1]; }
        float4 wa4 = Wa4[kc];
        float4 wd4 = Wd4[kc];
        float s[4];
        s[0] = silu(p4.x + q4.x + a * wa4.x + r * wd4.x);
        s[1] = silu(p4.y + q4.y + a * wa4.y + r * wd4.y);
        s[2] = silu(p4.z + q4.z + a * wa4.z + r * wd4.z);
        s[3] = silu(p4.w + q4.w + a * wa4.w + r * wd4.w);
#pragma unroll
        for (int u = 0; u < 4; u++) {
            const float4* wrow = reinterpret_cast<const float4*>(sW2 + (kc * 4 + u) * 32);
            float su = s[u];
#pragma unroll
            for (int c4 = 0; c4 < 8; c4++) {
                float4 w = wrow[c4];
                m[c4 * 4 + 0] += su * w.x;
                m[c4 * 4 + 1] += su * w.y;
                m[c4 * 4 + 2] += su * w.z;
                m[c4 * 4 + 3] += su * w.w;
            }
        }
        p4 = pn;
        q4 = qn;
    }
#pragma unroll
    for (int c = 0; c < 32; c++) m[c] = silu(m[c]);

    float* dst = mi + (size_t)i * 32;
#pragma unroll
    for (int c = 0; c < 32; c++) atomicAdd(dst + c, m[c]);
}

// ---------------- node MLP: feats' = silu([feats, m_i]@nW1+nb1)@nW2+nb2
// block = 256 (8 warps); each warp handles 2 nodes -> 16 nodes/block
template <int FI>
__global__ void node_kernel(const float* __restrict__ featsrc, int lds,
                            const float* __restrict__ mi,
                            const float* __restrict__ W1, const float* __restrict__ b1,
                            const float* __restrict__ W2, const float* __restrict__ b2,
                            float* __restrict__ featdst) {
    constexpr int CAT = FI + 32;
    __shared__ float scat[16][CAT];
    __shared__ float sh[16][64];
    int warp = threadIdx.x >> 5;
    int lane = threadIdx.x & 31;
    int na = blockIdx.x * 16 + warp * 2;
    int nb = na + 1;
#pragma unroll
    for (int u = 0; u < 2; u++) {
        int n = na + u;
        for (int idx = lane; idx < CAT; idx += 32) {
            float v = (idx < FI) ? featsrc[(size_t)n * lds + idx]
                                 : mi[(size_t)n * 32 + (idx - FI)];
            scat[warp * 2 + u][idx] = v;
        }
    }
    __syncwarp();
    float a0 = b1[lane], a1 = b1[lane + 32];
    float c0 = a0, c1 = a1;
    for (int f = 0; f < CAT; f++) {
        float w0 = W1[f * 64 + lane];
        float w1 = W1[f * 64 + lane + 32];
        float xa = scat[warp * 2][f];
        float xb = scat[warp * 2 + 1][f];
        a0 += xa * w0; a1 += xa * w1;
        c0 += xb * w0; c1 += xb * w1;
    }
    sh[warp * 2][lane] = silu(a0);
    sh[warp * 2][lane + 32] = silu(a1);
    sh[warp * 2 + 1][lane] = silu(c0);
    sh[warp * 2 + 1][lane + 32] = silu(c1);
    __syncwarp();
    float oa = b2[lane], ob = oa;
    for (int k = 0; k < 64; k++) {
        float w = W2[k * 32 + lane];
        oa += sh[warp * 2][k] * w;
        ob += sh[warp * 2 + 1][k] * w;
    }
    featdst[(size_t)na * 32 + lane] = oa;
    featdst[(size_t)nb * 32 + lane] = ob;
}

// ---------------- pooling: per-node dot with linW, segment-sum by batch -----
__global__ void pool_kernel(const float* __restrict__ feats, const int* __restrict__ batch,
                            const float* __restrict__ linW,
                            float* __restrict__ gsum, float* __restrict__ gcnt) {
    __shared__ float sw[32];
    if (threadIdx.x < 32) sw[threadIdx.x] = linW[threadIdx.x];
    __syncthreads();
    int n = blockIdx.x * blockDim.x + threadIdx.x;
    if (n >= Nn) return;
    const float4* fr = reinterpret_cast<const float4*>(feats + (size_t)n * 32);
    const float4* w4 = reinterpret_cast<const float4*>(sw);
    float s = 0.0f;
#pragma unroll
    for (int c4 = 0; c4 < 8; c4++) {
        float4 f = fr[c4];
        float4 w = w4[c4];
        s += f.x * w.x + f.y * w.y + f.z * w.z + f.w * w.w;
    }
    int g = batch[n];
    atomicAdd(&gsum[g], s);
    atomicAdd(&gcnt[g], 1.0f);
}

__global__ void finalize_kernel(const float* __restrict__ gsum, const float* __restrict__ gcnt,
                                const float* __restrict__ linb, float* __restrict__ out) {
    int g = threadIdx.x;
    if (g < Gg) out[g] = gsum[g] / fmaxf(gcnt[g], 1.0f) + linb[0];
}

// ---------------- host launcher ----------------------------------------------
extern "C" void kernel_launch(void* const* d_in, const int* in_sizes, int n_in,
                              void* d_out, int out_size) {
    const float* x = (const float*)d_in[0];
    const int* ei;
    const float* ea;
    const float* pos;
    // Disambiguate metadata order: signature order -> d_in[1] is edge_index (2*E ints),
    // dict order -> d_in[1] is positions (N*2 floats).
    if (in_sizes[1] == 2 * Ee) {
        ei = (const int*)d_in[1];
        ea = (const float*)d_in[2];
        pos = (const float*)d_in[3];
    } else {
        pos = (const float*)d_in[1];
        ei = (const int*)d_in[2];
        ea = (const float*)d_in[3];
    }
    const int* batch = (const int*)d_in[4];
    const float* W[26];
    for (int k = 0; k < 26; k++) W[k] = (const float*)d_in[5 + k];
    // per layer l (0-based), base = l*8: eW1, eb1, eW2, eb2, nW1, nb1, nW2, nb2
    const float* linW = W[24];
    const float* linb = W[25];

    float *P, *Q, *mi, *f0, *f1, *rd, *gs, *gc;
    cudaGetSymbolAddress((void**)&P, g_P);
    cudaGetSymbolAddress((void**)&Q, g_Q);
    cudaGetSymbolAddress((void**)&mi, g_m);
    cudaGetSymbolAddress((void**)&f0, g_f0);
    cudaGetSymbolAddress((void**)&f1, g_f1);
    cudaGetSymbolAddress((void**)&rd, g_rd);
    cudaGetSymbolAddress((void**)&gs, g_gsum);
    cudaGetSymbolAddress((void**)&gc, g_gcnt);

    const int EB = Ee / 256;       // 6250
    const int ZB = (Nn * 32) / 256; // 12500
    const int NB = Nn / 16;        // 6250 (node kernel)
    const int PB = (Nn + 255) / 256;

    rd_kernel<<<EB, 256>>>(ei, pos, rd);
    zero_pool_kernel<<<1, 128>>>(gs, gc);

    // ---- layer 1: FI=2, H=12 ----
    pre_kernel<2, 12><<<dim3(1, Nn / 4), 32>>>(x, 2, W[0], W[1], P, Q);
    zero_kernel<<<ZB, 256>>>(mi, Nn * 32);
    edge_kernel<12><<<EB, 256>>>(ei, ea, rd, P, Q, W[0] + 4 * 12, W[0] + 5 * 12,
                                 W[2], W[3], mi);
    node_kernel<2><<<NB, 256>>>(x, 2, mi, W[4], W[5], W[6], W[7], f0);

    // ---- layer 2: FI=32, H=132 ----
    pre_kernel<32, 132><<<dim3(1, Nn / 4), 160>>>(f0, 32, W[8], W[9], P, Q);
    zero_kernel<<<ZB, 256>>>(mi, Nn * 32);
    edge_kernel<132><<<EB, 256>>>(ei, ea, rd, P, Q, W[8] + 64 * 132, W[8] + 65 * 132,
                                  W[10], W[11], mi);
    node_kernel<32><<<NB, 256>>>(f0, 32, mi, W[12], W[13], W[14], W[15], f1);

    // ---- layer 3: FI=32, H=132 ----
    pre_kernel<32, 132><<<dim3(1, Nn / 4), 160>>>(f1, 32, W[16], W[17], P, Q);
    zero_kernel<<<ZB, 256>>>(mi, Nn * 32);
    edge_kernel<132><<<EB, 256>>>(ei, ea, rd, P, Q, W[16] + 64 * 132, W[16] + 65 * 132,
                                  W[18], W[19], mi);
    node_kernel<32><<<NB, 256>>>(f1, 32, mi, W[20], W[21], W[22], W[23], f0);

    // ---- pool + head ----
    pool_kernel<<<PB, 256>>>(f0, batch, linW, gs, gc);
    finalize_kernel<<<1, 128>>>(gs, gc, linb, (float*)d_out);
}

// round 2
// speedup vs baseline: 1.3995x; 1.3995x over previous
#include <cuda_runtime.h>
#include <cuda_fp16.h>
#include <cstddef>

#define Nn 100000
#define Ee 1600000
#define Gg 100

typedef unsigned long long ull;

// ---------------- scratch (device globals; no allocation allowed) ----------
__device__ __half g_P[(size_t)Nn * 136];
__device__ __half g_Q[(size_t)Nn * 136];
__device__ float g_m[(size_t)Nn * 32];
__device__ float g_f0[(size_t)Nn * 32];
__device__ float g_f1[(size_t)Nn * 32];
__device__ float g_rd[Ee];
__device__ float g_gsum[Gg];
__device__ float g_gcnt[Gg];

__device__ __forceinline__ float silu(float v) {
    float e = __expf(-v);
    return __fdividef(v, 1.0f + e);
}

// ---- packed f32x2 helpers (Blackwell-only; ptxas never auto-fuses these) ----
__device__ __forceinline__ ull pk2(float lo, float hi) {
    ull r; asm("mov.b64 %0, {%1, %2};" : "=l"(r) : "f"(lo), "f"(hi)); return r;
}
__device__ __forceinline__ ull splat2(float v) { return pk2(v, v); }
__device__ __forceinline__ void upk2(float& lo, float& hi, ull v) {
    asm("mov.b64 {%0, %1}, %2;" : "=f"(lo), "=f"(hi) : "l"(v));
}
__device__ __forceinline__ ull fma2(ull a, ull b, ull c) {
    ull d; asm("fma.rn.f32x2 %0, %1, %2, %3;" : "=l"(d) : "l"(a), "l"(b), "l"(c)); return d;
}

// ---------------- rel_dist (shared by all 3 layers) -------------------------
__global__ void rd_kernel(const int* __restrict__ ei, const float* __restrict__ pos,
                          float* __restrict__ rd) {
    int e = blockIdx.x * blockDim.x + threadIdx.x;
    if (e >= Ee) return;
    int j = ei[e];
    int i = ei[Ee + e];
    float2 pj = reinterpret_cast<const float2*>(pos)[j];
    float2 pi = reinterpret_cast<const float2*>(pos)[i];
    float dx = pj.x - pi.x, dy = pj.y - pi.y;
    rd[e] = dx * dx + dy * dy;
}

// ---------------- zero helpers ----------------------------------------------
__global__ void zero4_kernel(float4* __restrict__ p, int n4) {
    int idx = blockIdx.x * blockDim.x + threadIdx.x;
    if (idx < n4) p[idx] = make_float4(0.f, 0.f, 0.f, 0.f);
}
__global__ void zero_pool_kernel(float* __restrict__ gs, float* __restrict__ gc) {
    int t = threadIdx.x;
    if (t < Gg) { gs[t] = 0.0f; gc[t] = 0.0f; }
}

// ---------------- per-node projection: P = feats@W1[0:FI]+b1, Q = feats@W1[FI:2FI]
// output fp16 with padded stride HP (pad lanes = 0 -> contribute exactly 0 downstream)
template <int FI, int H, int HP>
__global__ void pre_kernel(const float* __restrict__ featsrc, int lds,
                           const float* __restrict__ W1, const float* __restrict__ b1,
                           __half* __restrict__ P, __half* __restrict__ Q) {
    __shared__ float sf[4][FI];
    int n0 = blockIdx.y * 4;
    int t = threadIdx.x;
    if (t < 4 * FI) sf[t / FI][t % FI] = featsrc[(size_t)(n0 + t / FI) * lds + (t % FI)];
    __syncthreads();
    int h = t;
    if (h >= HP) return;
    float p[4], q[4];
    if (h < H) {
        float bb = b1[h];
#pragma unroll
        for (int u = 0; u < 4; u++) { p[u] = bb; q[u] = 0.0f; }
        for (int f = 0; f < FI; f++) {
            float wp = W1[f * H + h];
            float wq = W1[(FI + f) * H + h];
#pragma unroll
            for (int u = 0; u < 4; u++) {
                float xv = sf[u][f];
                p[u] += xv * wp;
                q[u] += xv * wq;
            }
        }
    } else {
#pragma unroll
        for (int u = 0; u < 4; u++) { p[u] = 0.0f; q[u] = 0.0f; }
    }
#pragma unroll
    for (int u = 0; u < 4; u++) {
        P[(size_t)(n0 + u) * HP + h] = __float2half_rn(p[u]);
        Q[(size_t)(n0 + u) * HP + h] = __float2half_rn(q[u]);
    }
}

// ---------------- edge kernel: m_ij = silu(silu(P_i + Q_j + a*wa + r*wd) @ W2 + b2)
// lane = edge; f32x2 accumulators; fp16 gathers; red.global.add.v4.f32 scatter
template <int H, int HP>
__global__ void __launch_bounds__(256) edge_kernel(
        const int* __restrict__ ei, const float* __restrict__ ea,
        const float* __restrict__ rd,
        const __half* __restrict__ P, const __half* __restrict__ Q,
        const float* __restrict__ wa, const float* __restrict__ wd,
        const float* __restrict__ W2, const float* __restrict__ b2,
        float* __restrict__ mi) {
    __shared__ __align__(16) float sWa[HP];
    __shared__ __align__(16) float sWd[HP];
    __shared__ __align__(16) float sW2[HP * 32];
    __shared__ __align__(16) float sb2[32];
    for (int idx = threadIdx.x; idx < HP; idx += blockDim.x) {
        sWa[idx] = (idx < H) ? wa[idx] : 0.0f;
        sWd[idx] = (idx < H) ? wd[idx] : 0.0f;
    }
    for (int idx = threadIdx.x; idx < HP * 32; idx += blockDim.x)
        sW2[idx] = (idx < H * 32) ? W2[idx] : 0.0f;
    if (threadIdx.x < 32) sb2[threadIdx.x] = b2[threadIdx.x];
    __syncthreads();

    int e = blockIdx.x * blockDim.x + threadIdx.x;
    if (e >= Ee) return;
    int j = ei[e];
    int i = ei[Ee + e];
    float a = ea[e];
    float r = rd[e];

    ull m2[16];
    const ull* b2u = reinterpret_cast<const ull*>(sb2);
#pragma unroll
    for (int c = 0; c < 16; c++) m2[c] = b2u[c];

    const uint4* Pr = reinterpret_cast<const uint4*>(P + (size_t)i * HP);
    const uint4* Qr = reinterpret_cast<const uint4*>(Q + (size_t)j * HP);
    constexpr int CH = HP / 8;

    uint4 pv = Pr[0];
    uint4 qv = Qr[0];
#pragma unroll 1
    for (int t = 0; t < CH; t++) {
        uint4 pc = pv, qc = qv;
        if (t + 1 < CH) { pv = Pr[t + 1]; qv = Qr[t + 1]; }

        const __half2* ph = reinterpret_cast<const __half2*>(&pc);
        const __half2* qh = reinterpret_cast<const __half2*>(&qc);
        float pf[8], qf[8];
#pragma unroll
        for (int u = 0; u < 4; u++) {
            float2 fp = __half22float2(ph[u]);
            float2 fq = __half22float2(qh[u]);
            pf[2 * u] = fp.x; pf[2 * u + 1] = fp.y;
            qf[2 * u] = fq.x; qf[2 * u + 1] = fq.y;
        }

        float4 waA = reinterpret_cast<const float4*>(sWa)[t * 2];
        float4 waB = reinterpret_cast<const float4*>(sWa)[t * 2 + 1];
        float4 wdA = reinterpret_cast<const float4*>(sWd)[t * 2];
        float4 wdB = reinterpret_cast<const float4*>(sWd)[t * 2 + 1];
        float wav[8] = {waA.x, waA.y, waA.z, waA.w, waB.x, waB.y, waB.z, waB.w};
        float wdv[8] = {wdA.x, wdA.y, wdA.z, wdA.w, wdB.x, wdB.y, wdB.z, wdB.w};

        float s[8];
#pragma unroll
        for (int u = 0; u < 8; u++) {
            float h = pf[u] + qf[u];
            h = fmaf(a, wav[u], h);
            h = fmaf(r, wdv[u], h);
            s[u] = silu(h);
        }

#pragma unroll
        for (int u = 0; u < 8; u++) {
            ull s2 = splat2(s[u]);
            const ulonglong2* wr =
                reinterpret_cast<const ulonglong2*>(sW2 + (t * 8 + u) * 32);
#pragma unroll
            for (int c = 0; c < 8; c++) {
                ulonglong2 w = wr[c];
                m2[2 * c]     = fma2(s2, w.x, m2[2 * c]);
                m2[2 * c + 1] = fma2(s2, w.y, m2[2 * c + 1]);
            }
        }
    }

    float mo[32];
#pragma unroll
    for (int c = 0; c < 16; c++) upk2(mo[2 * c], mo[2 * c + 1], m2[c]);
#pragma unroll
    for (int c = 0; c < 32; c++) mo[c] = silu(mo[c]);

    float* dst = mi + (size_t)i * 32;
#pragma unroll
    for (int g = 0; g < 8; g++) {
        asm volatile("red.global.add.v4.f32 [%0], {%1, %2, %3, %4};"
                     :: "l"(dst + g * 4),
                        "f"(mo[4 * g]), "f"(mo[4 * g + 1]),
                        "f"(mo[4 * g + 2]), "f"(mo[4 * g + 3])
                     : "memory");
    }
}

// ---------------- node MLP: feats' = silu([feats, m_i]@nW1+nb1)@nW2+nb2
template <int FI>
__global__ void node_kernel(const float* __restrict__ featsrc, int lds,
                            const float* __restrict__ mi,
                            const float* __restrict__ W1, const float* __restrict__ b1,
                            const float* __restrict__ W2, const float* __restrict__ b2,
                            float* __restrict__ featdst) {
    constexpr int CAT = FI + 32;
    __shared__ float scat[16][CAT];
    __shared__ float sh[16][64];
    int warp = threadIdx.x >> 5;
    int lane = threadIdx.x & 31;
    int na = blockIdx.x * 16 + warp * 2;
    int nb = na + 1;
#pragma unroll
    for (int u = 0; u < 2; u++) {
        int n = na + u;
        for (int idx = lane; idx < CAT; idx += 32) {
            float v = (idx < FI) ? featsrc[(size_t)n * lds + idx]
                                 : mi[(size_t)n * 32 + (idx - FI)];
            scat[warp * 2 + u][idx] = v;
        }
    }
    __syncwarp();
    float a0 = b1[lane], a1 = b1[lane + 32];
    float c0 = a0, c1 = a1;
    for (int f = 0; f < CAT; f++) {
        float w0 = W1[f * 64 + lane];
        float w1 = W1[f * 64 + lane + 32];
        float xa = scat[warp * 2][f];
        float xb = scat[warp * 2 + 1][f];
        a0 += xa * w0; a1 += xa * w1;
        c0 += xb * w0; c1 += xb * w1;
    }
    sh[warp * 2][lane] = silu(a0);
    sh[warp * 2][lane + 32] = silu(a1);
    sh[warp * 2 + 1][lane] = silu(c0);
    sh[warp * 2 + 1][lane + 32] = silu(c1);
    __syncwarp();
    float oa = b2[lane], ob = oa;
    for (int k = 0; k < 64; k++) {
        float w = W2[k * 32 + lane];
        oa += sh[warp * 2][k] * w;
        ob += sh[warp * 2 + 1][k] * w;
    }
    featdst[(size_t)na * 32 + lane] = oa;
    featdst[(size_t)nb * 32 + lane] = ob;
}

// ---------------- pooling ----------------------------------------------------
__global__ void pool_kernel(const float* __restrict__ feats, const int* __restrict__ batch,
                            const float* __restrict__ linW,
                            float* __restrict__ gsum, float* __restrict__ gcnt) {
    __shared__ float sw[32];
    if (threadIdx.x < 32) sw[threadIdx.x] = linW[threadIdx.x];
    __syncthreads();
    int n = blockIdx.x * blockDim.x + threadIdx.x;
    if (n >= Nn) return;
    const float4* fr = reinterpret_cast<const float4*>(feats + (size_t)n * 32);
    const float4* w4 = reinterpret_cast<const float4*>(sw);
    float s = 0.0f;
#pragma unroll
    for (int c4 = 0; c4 < 8; c4++) {
        float4 f = fr[c4];
        float4 w = w4[c4];
        s += f.x * w.x + f.y * w.y + f.z * w.z + f.w * w.w;
    }
    int g = batch[n];
    atomicAdd(&gsum[g], s);
    atomicAdd(&gcnt[g], 1.0f);
}

__global__ void finalize_kernel(const float* __restrict__ gsum, const float* __restrict__ gcnt,
                                const float* __restrict__ linb, float* __restrict__ out) {
    int g = threadIdx.x;
    if (g < Gg) out[g] = gsum[g] / fmaxf(gcnt[g], 1.0f) + linb[0];
}

// ---------------- host launcher ----------------------------------------------
extern "C" void kernel_launch(void* const* d_in, const int* in_sizes, int n_in,
                              void* d_out, int out_size) {
    const float* x = (const float*)d_in[0];
    const int* ei;
    const float* ea;
    const float* pos;
    if (in_sizes[1] == 2 * Ee) {
        ei = (const int*)d_in[1];
        ea = (const float*)d_in[2];
        pos = (const float*)d_in[3];
    } else {
        pos = (const float*)d_in[1];
        ei = (const int*)d_in[2];
        ea = (const float*)d_in[3];
    }
    const int* batch = (const int*)d_in[4];
    const float* W[26];
    for (int k = 0; k < 26; k++) W[k] = (const float*)d_in[5 + k];
    const float* linW = W[24];
    const float* linb = W[25];

    __half *P, *Q;
    float *mi, *f0, *f1, *rd, *gs, *gc;
    cudaGetSymbolAddress((void**)&P, g_P);
    cudaGetSymbolAddress((void**)&Q, g_Q);
    cudaGetSymbolAddress((void**)&mi, g_m);
    cudaGetSymbolAddress((void**)&f0, g_f0);
    cudaGetSymbolAddress((void**)&f1, g_f1);
    cudaGetSymbolAddress((void**)&rd, g_rd);
    cudaGetSymbolAddress((void**)&gs, g_gsum);
    cudaGetSymbolAddress((void**)&gc, g_gcnt);

    const int EB = Ee / 256;            // 6250
    const int ZB4 = (Nn * 32 / 4) / 256; // 3125
    const int NB = Nn / 16;             // 6250
    const int PB = (Nn + 255) / 256;

    rd_kernel<<<EB, 256>>>(ei, pos, rd);
    zero_pool_kernel<<<1, 128>>>(gs, gc);

    // ---- layer 1: FI=2, H=12 (HP=16) ----
    pre_kernel<2, 12, 16><<<dim3(1, Nn / 4), 32>>>(x, 2, W[0], W[1], P, Q);
    zero4_kernel<<<ZB4, 256>>>((float4*)mi, Nn * 32 / 4);
    edge_kernel<12, 16><<<EB, 256>>>(ei, ea, rd, P, Q, W[0] + 4 * 12, W[0] + 5 * 12,
                                     W[2], W[3], mi);
    node_kernel<2><<<NB, 256>>>(x, 2, mi, W[4], W[5], W[6], W[7], f0);

    // ---- layer 2: FI=32, H=132 (HP=136) ----
    pre_kernel<32, 132, 136><<<dim3(1, Nn / 4), 160>>>(f0, 32, W[8], W[9], P, Q);
    zero4_kernel<<<ZB4, 256>>>((float4*)mi, Nn * 32 / 4);
    edge_kernel<132, 136><<<EB, 256>>>(ei, ea, rd, P, Q, W[8] + 64 * 132, W[8] + 65 * 132,
                                       W[10], W[11], mi);
    node_kernel<32><<<NB, 256>>>(f0, 32, mi, W[12], W[13], W[14], W[15], f1);

    // ---- layer 3: FI=32, H=132 (HP=136) ----
    pre_kernel<32, 132, 136><<<dim3(1, Nn / 4), 160>>>(f1, 32, W[16], W[17], P, Q);
    zero4_kernel<<<ZB4, 256>>>((float4*)mi, Nn * 32 / 4);
    edge_kernel<132, 136><<<EB, 256>>>(ei, ea, rd, P, Q, W[16] + 64 * 132, W[16] + 65 * 132,
                                       W[18], W[19], mi);
    node_kernel<32><<<NB, 256>>>(f1, 32, mi, W[20], W[21], W[22], W[23], f0);

    // ---- pool + head ----
    pool_kernel<<<PB, 256>>>(f0, batch, linW, gs, gc);
    finalize_kernel<<<1, 128>>>(gs, gc, linb, (float*)d_out);
}

// round 3
// speedup vs baseline: 1.4126x; 1.0093x over previous
#include <cuda_runtime.h>
#include <cuda_fp16.h>
#include <cstddef>

#define Nn 100000
#define Ee 1600000
#define Gg 100
#define NSCAN 98   // ceil(Nn/1024)

typedef unsigned long long ull;

// ---------------- scratch (device globals; no allocation allowed) ----------
__device__ __half g_P[(size_t)Nn * 136];
__device__ __half g_Q[(size_t)Nn * 136];
__device__ float g_m[(size_t)Nn * 32];
__device__ float g_f0[(size_t)Nn * 32];
__device__ float g_f1[(size_t)Nn * 32];
__device__ int g_cnt[Nn];
__device__ int g_off[Nn];
__device__ int g_bsum[NSCAN + 1];
__device__ int g_sI[Ee];
__device__ int g_sJ[Ee];
__device__ float2 g_sAR[Ee];
__device__ float g_gsum[Gg];
__device__ float g_gcnt[Gg];

__device__ __forceinline__ float silu(float v) {
    float e = __expf(-v);
    return __fdividef(v, 1.0f + e);
}

// ---- packed f32x2 helpers (Blackwell; ptxas never auto-fuses these) --------
__device__ __forceinline__ ull pk2(float lo, float hi) {
    ull r; asm("mov.b64 %0, {%1, %2};" : "=l"(r) : "f"(lo), "f"(hi)); return r;
}
__device__ __forceinline__ ull splat2(float v) { return pk2(v, v); }
__device__ __forceinline__ void upk2(float& lo, float& hi, ull v) {
    asm("mov.b64 {%0, %1}, %2;" : "=f"(lo), "=f"(hi) : "l"(v));
}
__device__ __forceinline__ ull fma2(ull a, ull b, ull c) {
    ull d; asm("fma.rn.f32x2 %0, %1, %2, %3;" : "=l"(d) : "l"(a), "l"(b), "l"(c)); return d;
}

// ================= counting sort of edges by destination i ==================
__global__ void hist_kernel(const int* __restrict__ ei, int* __restrict__ cnt) {
    int e = blockIdx.x * blockDim.x + threadIdx.x;
    if (e < Ee) atomicAdd(&cnt[ei[Ee + e]], 1);
}

__global__ void scan1_kernel(const int* __restrict__ cnt, int* __restrict__ off,
                             int* __restrict__ bsum) {
    int idx = blockIdx.x * 1024 + threadIdx.x;
    int v = (idx < Nn) ? cnt[idx] : 0;
    int lane = threadIdx.x & 31, warp = threadIdx.x >> 5;
    int s = v;
#pragma unroll
    for (int d = 1; d < 32; d <<= 1) {
        int t = __shfl_up_sync(~0u, s, d);
        if (lane >= d) s += t;
    }
    __shared__ int ws[32];
    if (lane == 31) ws[warp] = s;
    __syncthreads();
    if (warp == 0) {
        int t = ws[lane];
#pragma unroll
        for (int d = 1; d < 32; d <<= 1) {
            int u = __shfl_up_sync(~0u, t, d);
            if (lane >= d) t += u;
        }
        ws[lane] = t;
    }
    __syncthreads();
    int incl = s + ((warp > 0) ? ws[warp - 1] : 0);
    if (idx < Nn) off[idx] = incl - v;      // exclusive within block
    if (threadIdx.x == 1023) bsum[blockIdx.x] = incl;
}

__global__ void scan2_kernel(int* __restrict__ bsum) {
    if (threadIdx.x == 0) {
        int run = 0;
        for (int b = 0; b < NSCAN; b++) { int t = bsum[b]; bsum[b] = run; run += t; }
    }
}

__global__ void scan3_kernel(int* __restrict__ off, const int* __restrict__ bsum) {
    int idx = blockIdx.x * 1024 + threadIdx.x;
    if (idx < Nn) off[idx] += bsum[blockIdx.x];
}

__global__ void scatter_kernel(const int* __restrict__ ei, const float* __restrict__ ea,
                               const float* __restrict__ pos, int* __restrict__ off,
                               int* __restrict__ sI, int* __restrict__ sJ,
                               float2* __restrict__ sAR) {
    int e = blockIdx.x * blockDim.x + threadIdx.x;
    if (e >= Ee) return;
    int j = ei[e];
    int i = ei[Ee + e];
    float2 pj = reinterpret_cast<const float2*>(pos)[j];
    float2 pi = reinterpret_cast<const float2*>(pos)[i];
    float dx = pj.x - pi.x, dy = pj.y - pi.y;
    int p = atomicAdd(&off[i], 1);
    sI[p] = i;
    sJ[p] = j;
    sAR[p] = make_float2(ea[e], dx * dx + dy * dy);
}

// ---------------- misc -------------------------------------------------------
__global__ void zero_pool_kernel(float* __restrict__ gs, float* __restrict__ gc) {
    int t = threadIdx.x;
    if (t < Gg) { gs[t] = 0.0f; gc[t] = 0.0f; }
}

// ---------------- per-node projection: P = feats@W1[0:FI]+b1, Q = feats@W1[FI:2FI]
// fp16 output, padded stride HP; 16 nodes per block, f32x2 (p,q) accumulation
template <int FI, int H, int HP>
__global__ void pre_kernel(const float* __restrict__ featsrc, int lds,
                           const float* __restrict__ W1, const float* __restrict__ b1,
                           __half* __restrict__ P, __half* __restrict__ Q) {
    __shared__ float sf[16][FI];
    int n0 = blockIdx.x * 16;
    int t = threadIdx.x;
    for (int idx = t; idx < 16 * FI; idx += blockDim.x)
        sf[idx / FI][idx % FI] = featsrc[(size_t)(n0 + idx / FI) * lds + (idx % FI)];
    __syncthreads();
    int h = t;
    if (h >= HP) return;
    ull pq[16];
    if (h < H) {
        ull init = pk2(b1[h], 0.0f);
#pragma unroll
        for (int u = 0; u < 16; u++) pq[u] = init;
        for (int f = 0; f < FI; f++) {
            ull w = pk2(W1[f * H + h], W1[(FI + f) * H + h]);
#pragma unroll
            for (int u = 0; u < 16; u++)
                pq[u] = fma2(splat2(sf[u][f]), w, pq[u]);
        }
    } else {
#pragma unroll
        for (int u = 0; u < 16; u++) pq[u] = 0;
    }
#pragma unroll
    for (int u = 0; u < 16; u++) {
        float p, q; upk2(p, q, pq[u]);
        P[(size_t)(n0 + u) * HP + h] = __float2half_rn(p);
        Q[(size_t)(n0 + u) * HP + h] = __float2half_rn(q);
    }
}

// ---------------- edge kernel (sorted by i): -------------------------------
// m_ij = silu(silu(P_i + Q_j + a*wa + r*wd) @ W2 + b2), scatter red.v4 into mi
template <int H, int HP>
__global__ void __launch_bounds__(256) edge_kernel(
        const int* __restrict__ sI, const int* __restrict__ sJ,
        const float2* __restrict__ sAR,
        const __half* __restrict__ P, const __half* __restrict__ Q,
        const float* __restrict__ wa, const float* __restrict__ wd,
        const float* __restrict__ W2, const float* __restrict__ b2,
        float* __restrict__ mi) {
    __shared__ __align__(16) float sWa[HP];
    __shared__ __align__(16) float sWd[HP];
    __shared__ __align__(16) float sW2[HP * 32];
    __shared__ __align__(16) float sb2[32];
    for (int idx = threadIdx.x; idx < HP; idx += blockDim.x) {
        sWa[idx] = (idx < H) ? wa[idx] : 0.0f;
        sWd[idx] = (idx < H) ? wd[idx] : 0.0f;
    }
    for (int idx = threadIdx.x; idx < HP * 32; idx += blockDim.x)
        sW2[idx] = (idx < H * 32) ? W2[idx] : 0.0f;
    if (threadIdx.x < 32) sb2[threadIdx.x] = b2[threadIdx.x];
    __syncthreads();

    int e = blockIdx.x * blockDim.x + threadIdx.x;
    if (e >= Ee) return;
    int i = sI[e];
    int j = sJ[e];
    float2 ar = sAR[e];
    float a = ar.x;
    float r = ar.y;

    ull m2[16];
    const ull* b2u = reinterpret_cast<const ull*>(sb2);
#pragma unroll
    for (int c = 0; c < 16; c++) m2[c] = b2u[c];

    const uint4* Pr = reinterpret_cast<const uint4*>(P + (size_t)i * HP);
    const uint4* Qr = reinterpret_cast<const uint4*>(Q + (size_t)j * HP);
    constexpr int CH = HP / 8;

    uint4 pv = Pr[0];
    uint4 qv = Qr[0];
#pragma unroll 1
    for (int t = 0; t < CH; t++) {
        uint4 pc = pv, qc = qv;
        if (t + 1 < CH) { pv = Pr[t + 1]; qv = Qr[t + 1]; }

        const __half2* ph = reinterpret_cast<const __half2*>(&pc);
        const __half2* qh = reinterpret_cast<const __half2*>(&qc);
        float pf[8], qf[8];
#pragma unroll
        for (int u = 0; u < 4; u++) {
            float2 fp = __half22float2(ph[u]);
            float2 fq = __half22float2(qh[u]);
            pf[2 * u] = fp.x; pf[2 * u + 1] = fp.y;
            qf[2 * u] = fq.x; qf[2 * u + 1] = fq.y;
        }

        float4 waA = reinterpret_cast<const float4*>(sWa)[t * 2];
        float4 waB = reinterpret_cast<const float4*>(sWa)[t * 2 + 1];
        float4 wdA = reinterpret_cast<const float4*>(sWd)[t * 2];
        float4 wdB = reinterpret_cast<const float4*>(sWd)[t * 2 + 1];
        float wav[8] = {waA.x, waA.y, waA.z, waA.w, waB.x, waB.y, waB.z, waB.w};
        float wdv[8] = {wdA.x, wdA.y, wdA.z, wdA.w, wdB.x, wdB.y, wdB.z, wdB.w};

        float s[8];
#pragma unroll
        for (int u = 0; u < 8; u++) {
            float h = pf[u] + qf[u];
            h = fmaf(a, wav[u], h);
            h = fmaf(r, wdv[u], h);
            s[u] = silu(h);
        }

#pragma unroll
        for (int u = 0; u < 8; u++) {
            ull s2 = splat2(s[u]);
            const ulonglong2* wr =
                reinterpret_cast<const ulonglong2*>(sW2 + (t * 8 + u) * 32);
#pragma unroll
            for (int c = 0; c < 8; c++) {
                ulonglong2 w = wr[c];
                m2[2 * c]     = fma2(s2, w.x, m2[2 * c]);
                m2[2 * c + 1] = fma2(s2, w.y, m2[2 * c + 1]);
            }
        }
    }

    float mo[32];
#pragma unroll
    for (int c = 0; c < 16; c++) upk2(mo[2 * c], mo[2 * c + 1], m2[c]);
#pragma unroll
    for (int c = 0; c < 32; c++) mo[c] = silu(mo[c]);

    float* dst = mi + (size_t)i * 32;
#pragma unroll
    for (int g = 0; g < 8; g++) {
        asm volatile("red.global.add.v4.f32 [%0], {%1, %2, %3, %4};"
                     :: "l"(dst + g * 4),
                        "f"(mo[4 * g]), "f"(mo[4 * g + 1]),
                        "f"(mo[4 * g + 2]), "f"(mo[4 * g + 3])
                     : "memory");
    }
}

// ---------------- node MLP: feats' = silu([feats, m_i]@nW1+nb1)@nW2+nb2
// smem-staged weights, 4 nodes/warp, f32x2 accumulators
template <int FI>
__global__ void __launch_bounds__(256) node_kernel(
        const float* __restrict__ featsrc, int lds,
        const float* __restrict__ mi,
        const float* __restrict__ W1, const float* __restrict__ b1,
        const float* __restrict__ W2, const float* __restrict__ b2,
        float* __restrict__ featdst) {
    constexpr int CAT = FI + 32;
    __shared__ float sW1[CAT * 64];
    __shared__ float sW2[64 * 32];
    __shared__ float sb1[64];
    __shared__ float sb2s[32];
    __shared__ float scat[32][CAT];
    __shared__ float sh[32][64];
    int t = threadIdx.x;
    for (int idx = t; idx < CAT * 64; idx += 256) sW1[idx] = W1[idx];
    for (int idx = t; idx < 64 * 32; idx += 256) sW2[idx] = W2[idx];
    if (t < 64) sb1[t] = b1[t];
    if (t < 32) sb2s[t] = b2[t];

    int warp = t >> 5, lane = t & 31;
    int n0 = blockIdx.x * 32 + warp * 4;
#pragma unroll
    for (int u = 0; u < 4; u++) {
        int n = n0 + u;
        for (int idx = lane; idx < CAT; idx += 32)
            scat[warp * 4 + u][idx] = (idx < FI) ? featsrc[(size_t)n * lds + idx]
                                                 : mi[(size_t)n * 32 + (idx - FI)];
    }
    __syncthreads();

    ull h2[4];
    ull binit = pk2(sb1[lane], sb1[lane + 32]);
#pragma unroll
    for (int u = 0; u < 4; u++) h2[u] = binit;
    for (int f = 0; f < CAT; f++) {
        ull w = pk2(sW1[f * 64 + lane], sW1[f * 64 + lane + 32]);
#pragma unroll
        for (int u = 0; u < 4; u++)
            h2[u] = fma2(splat2(scat[warp * 4 + u][f]), w, h2[u]);
    }
#pragma unroll
    for (int u = 0; u < 4; u++) {
        float lo, hi; upk2(lo, hi, h2[u]);
        sh[warp * 4 + u][lane] = silu(lo);
        sh[warp * 4 + u][lane + 32] = silu(hi);
    }
    __syncwarp();

    ull o01 = splat2(sb2s[lane]);
    ull o23 = o01;
    for (int k = 0; k < 64; k++) {
        ull wv = splat2(sW2[k * 32 + lane]);
        ull x01 = pk2(sh[warp * 4 + 0][k], sh[warp * 4 + 1][k]);
        ull x23 = pk2(sh[warp * 4 + 2][k], sh[warp * 4 + 3][k]);
        o01 = fma2(x01, wv, o01);
        o23 = fma2(x23, wv, o23);
    }
    float o0, o1, o2, o3;
    upk2(o0, o1, o01);
    upk2(o2, o3, o23);
    featdst[(size_t)(n0 + 0) * 32 + lane] = o0;
    featdst[(size_t)(n0 + 1) * 32 + lane] = o1;
    featdst[(size_t)(n0 + 2) * 32 + lane] = o2;
    featdst[(size_t)(n0 + 3) * 32 + lane] = o3;
}

// ---------------- pooling ----------------------------------------------------
__global__ void pool_kernel(const float* __restrict__ feats, const int* __restrict__ batch,
                            const float* __restrict__ linW,
                            float* __restrict__ gsum, float* __restrict__ gcnt) {
    __shared__ float sw[32];
    if (threadIdx.x < 32) sw[threadIdx.x] = linW[threadIdx.x];
    __syncthreads();
    int n = blockIdx.x * blockDim.x + threadIdx.x;
    if (n >= Nn) return;
    const float4* fr = reinterpret_cast<const float4*>(feats + (size_t)n * 32);
    const float4* w4 = reinterpret_cast<const float4*>(sw);
    float s = 0.0f;
#pragma unroll
    for (int c4 = 0; c4 < 8; c4++) {
        float4 f = fr[c4];
        float4 w = w4[c4];
        s += f.x * w.x + f.y * w.y + f.z * w.z + f.w * w.w;
    }
    int g = batch[n];
    atomicAdd(&gsum[g], s);
    atomicAdd(&gcnt[g], 1.0f);
}

__global__ void finalize_kernel(const float* __restrict__ gsum, const float* __restrict__ gcnt,
                                const float* __restrict__ linb, float* __restrict__ out) {
    int g = threadIdx.x;
    if (g < Gg) out[g] = gsum[g] / fmaxf(gcnt[g], 1.0f) + linb[0];
}

// ---------------- host launcher ----------------------------------------------
extern "C" void kernel_launch(void* const* d_in, const int* in_sizes, int n_in,
                              void* d_out, int out_size) {
    const float* x = (const float*)d_in[0];
    const int* ei;
    const float* ea;
    const float* pos;
    if (in_sizes[1] == 2 * Ee) {
        ei = (const int*)d_in[1];
        ea = (const float*)d_in[2];
        pos = (const float*)d_in[3];
    } else {
        pos = (const float*)d_in[1];
        ei = (const int*)d_in[2];
        ea = (const float*)d_in[3];
    }
    const int* batch = (const int*)d_in[4];
    const float* W[26];
    for (int k = 0; k < 26; k++) W[k] = (const float*)d_in[5 + k];
    const float* linW = W[24];
    const float* linb = W[25];

    __half *P, *Q;
    float *mi, *f0, *f1, *gs, *gc;
    int *cnt, *off, *bsum, *sI, *sJ;
    float2* sAR;
    cudaGetSymbolAddress((void**)&P, g_P);
    cudaGetSymbolAddress((void**)&Q, g_Q);
    cudaGetSymbolAddress((void**)&mi, g_m);
    cudaGetSymbolAddress((void**)&f0, g_f0);
    cudaGetSymbolAddress((void**)&f1, g_f1);
    cudaGetSymbolAddress((void**)&cnt, g_cnt);
    cudaGetSymbolAddress((void**)&off, g_off);
    cudaGetSymbolAddress((void**)&bsum, g_bsum);
    cudaGetSymbolAddress((void**)&sI, g_sI);
    cudaGetSymbolAddress((void**)&sJ, g_sJ);
    cudaGetSymbolAddress((void**)&sAR, g_sAR);
    cudaGetSymbolAddress((void**)&gs, g_gsum);
    cudaGetSymbolAddress((void**)&gc, g_gcnt);

    const int EB = Ee / 256;   // 6250
    const int PREB = Nn / 16;  // 6250
    const int NB = Nn / 32;    // 3125
    const int PB = (Nn + 255) / 256;

    // ---- sort edges by destination i (reused by all 3 layers) ----
    cudaMemsetAsync(cnt, 0, Nn * sizeof(int));
    hist_kernel<<<EB, 256>>>(ei, cnt);
    scan1_kernel<<<NSCAN, 1024>>>(cnt, off, bsum);
    scan2_kernel<<<1, 32>>>(bsum);
    scan3_kernel<<<NSCAN, 1024>>>(off, bsum);
    scatter_kernel<<<EB, 256>>>(ei, ea, pos, off, sI, sJ, sAR);
    zero_pool_kernel<<<1, 128>>>(gs, gc);

    // ---- layer 1: FI=2, H=12 (HP=16) ----
    pre_kernel<2, 12, 16><<<PREB, 32>>>(x, 2, W[0], W[1], P, Q);
    cudaMemsetAsync(mi, 0, (size_t)Nn * 32 * sizeof(float));
    edge_kernel<12, 16><<<EB, 256>>>(sI, sJ, sAR, P, Q, W[0] + 4 * 12, W[0] + 5 * 12,
                                     W[2], W[3], mi);
    node_kernel<2><<<NB, 256>>>(x, 2, mi, W[4], W[5], W[6], W[7], f0);

    // ---- layer 2: FI=32, H=132 (HP=136) ----
    pre_kernel<32, 132, 136><<<PREB, 160>>>(f0, 32, W[8], W[9], P, Q);
    cudaMemsetAsync(mi, 0, (size_t)Nn * 32 * sizeof(float));
    edge_kernel<132, 136><<<EB, 256>>>(sI, sJ, sAR, P, Q, W[8] + 64 * 132, W[8] + 65 * 132,
                                       W[10], W[11], mi);
    node_kernel<32><<<NB, 256>>>(f0, 32, mi, W[12], W[13], W[14], W[15], f1);

    // ---- layer 3: FI=32, H=132 (HP=136) ----
    pre_kernel<32, 132, 136><<<PREB, 160>>>(f1, 32, W[16], W[17], P, Q);
    cudaMemsetAsync(mi, 0, (size_t)Nn * 32 * sizeof(float));
    edge_kernel<132, 136><<<EB, 256>>>(sI, sJ, sAR, P, Q, W[16] + 64 * 132, W[16] + 65 * 132,
                                       W[18], W[19], mi);
    node_kernel<32><<<NB, 256>>>(f1, 32, mi, W[20], W[21], W[22], W[23], f0);

    // ---- pool + head ----
    pool_kernel<<<PB, 256>>>(f0, batch, linW, gs, gc);
    finalize_kernel<<<1, 128>>>(gs, gc, linb, (float*)d_out);
}